// round 6
// baseline (speedup 1.0000x reference)
#include <cuda_runtime.h>
#include <cuda_bf16.h>
#include <math.h>
#include <cstdint>

// Problem dims (fixed)
#define BT_  8
#define L_   8192
#define M_TOT 65536            // BT_*L_
#define NC   64                // chunks per sequence
#define LCH  128               // L_/NC
#define LOG_LCH 7
#define NCHAIN 2048            // BT_*NC*4 bn-tiles = total chunk-tiles

// ---------------------------------------------------------------------------
// Scratch (device globals — allocation-free per harness rules)
// ---------------------------------------------------------------------------
__device__ __nv_bfloat16 g_xh[(size_t)M_TOT * 512];  // x split hi
__device__ __nv_bfloat16 g_xl[(size_t)M_TOT * 512];  // x split lo
__device__ __nv_bfloat16 g_yh[(size_t)M_TOT * 512];  // ys split hi
__device__ __nv_bfloat16 g_yl[(size_t)M_TOT * 512];  // ys split lo
__device__ __nv_bfloat16 g_W1h[512 * 512];        // GEMM1 weight [n=2p+c][h]
__device__ __nv_bfloat16 g_W1l[512 * 512];
__device__ __nv_bfloat16 g_W2h[512 * 512];        // GEMM2 weight [n=h][k=2p+c]
__device__ __nv_bfloat16 g_W2l[512 * 512];
// decoupled-lookback state: per (ticket)(worker p)  (z1R,z2R,z1I,z2I)
__device__ float4 g_agg[NCHAIN * 64];
__device__ float4 g_incl[NCHAIN * 64];
__device__ int g_flag[NCHAIN];
__device__ unsigned int g_ticket;

// ---------------------------------------------------------------------------
// Helpers (sm_80-level: cp.async / ldmatrix / mma.sync — legal on sm_100)
// ---------------------------------------------------------------------------
__device__ __forceinline__ uint32_t smem_u32(const void* p) {
    uint32_t a;
    asm("{ .reg .u64 t; cvta.to.shared.u64 t, %1; cvt.u32.u64 %0, t; }" : "=r"(a) : "l"(p));
    return a;
}
__device__ __forceinline__ uint32_t swz(uint32_t off) { return off ^ ((off >> 3) & 0x70); }

#define CP_ASYNC16(dst_u32, src_ptr) \
    asm volatile("cp.async.cg.shared.global [%0], [%1], 16;" \
                 :: "r"(dst_u32), "l"(src_ptr) : "memory")
#define CP_COMMIT() asm volatile("cp.async.commit_group;" ::: "memory")
#define CP_WAIT1()  asm volatile("cp.async.wait_group 1;" ::: "memory")
#define CP_WAIT0()  asm volatile("cp.async.wait_group 0;" ::: "memory")
#define BAR64() asm volatile("bar.sync 1, 64;" ::: "memory")

#define LDSM4(r, addr) \
    asm volatile("ldmatrix.sync.aligned.m8n8.x4.shared.b16 {%0,%1,%2,%3}, [%4];" \
                 : "=r"((r)[0]), "=r"((r)[1]), "=r"((r)[2]), "=r"((r)[3]) : "r"(addr))

__device__ __forceinline__ void mma16816(float* d, const uint32_t* a, uint32_t b0, uint32_t b1) {
    asm volatile("mma.sync.aligned.m16n8k16.row.col.f32.bf16.bf16.f32 "
                 "{%0,%1,%2,%3}, {%4,%5,%6,%7}, {%8,%9}, {%0,%1,%2,%3};"
                 : "+f"(d[0]), "+f"(d[1]), "+f"(d[2]), "+f"(d[3])
                 : "r"(a[0]), "r"(a[1]), "r"(a[2]), "r"(a[3]), "r"(b0), "r"(b1));
}

__device__ __forceinline__ uint32_t bf16_bits(float v) {
    return (uint32_t)__bfloat16_as_ushort(__float2bfloat16_rn(v));
}
__device__ __forceinline__ uint32_t pack_hi_lo(float a, float b, uint32_t& lo_out) {
    uint32_t ha = bf16_bits(a), hb = bf16_bits(b);
    float ra = __bfloat162float(__ushort_as_bfloat16((unsigned short)ha));
    float rb = __bfloat162float(__ushort_as_bfloat16((unsigned short)hb));
    uint32_t la = bf16_bits(a - ra), lb = bf16_bits(b - rb);
    lo_out = la | (lb << 16);
    return ha | (hb << 16);
}

// ---------------------------------------------------------------------------
// Prep kernels
// ---------------------------------------------------------------------------
__device__ __forceinline__ void split_store(__nv_bfloat16* Wh, __nv_bfloat16* Wl,
                                            size_t idx, float v) {
    __nv_bfloat16 h = __float2bfloat16_rn(v);
    Wh[idx] = h;
    Wl[idx] = __float2bfloat16_rn(v - __bfloat162float(h));
}
__global__ void prep_weights(const float* __restrict__ B, const float* __restrict__ C)
{
    int i = blockIdx.x * blockDim.x + threadIdx.x;  // 0 .. 131071
    int p = i >> 9;
    int h = i & 511;
    float br = B[((p << 9) + h) * 2 + 0];
    float bi = B[((p << 9) + h) * 2 + 1];
    float cr = C[((h << 8) + p) * 2 + 0];
    float ci = -C[((h << 8) + p) * 2 + 1];
    split_store(g_W1h, g_W1l, (size_t)(2 * p) * 512 + h, br);
    split_store(g_W1h, g_W1l, (size_t)(2 * p + 1) * 512 + h, bi);
    split_store(g_W2h, g_W2l, (size_t)(h << 9) + 2 * p, cr);
    split_store(g_W2h, g_W2l, (size_t)(h << 9) + 2 * p + 1, ci);
}

__global__ void prep_x(const float* __restrict__ x)
{
    // also reset lookback state for this launch (graph-replay safe)
    if (blockIdx.x == 0) {
        if (threadIdx.x == 0) g_ticket = 0u;
        for (int i = threadIdx.x; i < NCHAIN; i += 256) g_flag[i] = 0;
    }
    size_t i = (size_t)blockIdx.x * 256 + threadIdx.x;  // float4 units
    float4 v = ((const float4*)x)[i];
    uint32_t l0, l1;
    uint32_t h0 = pack_hi_lo(v.x, v.y, l0);
    uint32_t h1 = pack_hi_lo(v.z, v.w, l1);
    ((uint2*)g_xh)[i] = make_uint2(h0, h1);
    ((uint2*)g_xl)[i] = make_uint2(l0, l1);
}

// ---------------------------------------------------------------------------
// Transition parameters (reference fp32 rounding; sigmoid in double)
// ---------------------------------------------------------------------------
__device__ __forceinline__ void get_params(const float* __restrict__ sp,
                                           const float* __restrict__ ap, int p,
                                           float& s, float& s2,
                                           float& mB, float& mC, float& mD)
{
    double sd = 1.0 / (1.0 + exp(-(double)sp[p]));
    s = (float)sd;
    float a = fmaxf(ap[p], 0.0f);
    mB = -__fmul_rn(s, a);
    mC = s;
    s2 = __fmul_rn(s, s);
    mD = __fsub_rn(1.0f, __fmul_rn(s2, a));
}

// ---------------------------------------------------------------------------
// Fused GEMM1 + associative scan (decoupled lookback).
//   Bu tile (128 rows = one scan chunk, 128 cols = 64 p's) never leaves the CTA:
//   MMA -> smem stage -> local scan -> lookback prefix -> rescan -> ys bf16 hi/lo.
// Stage layout (64KB each, 2 stages): Ah +0, Al +16K, Wh +32K, Wl +48K; SW128.
// After mainloop the stage memory is reused as a 128 x 132-float scan buffer.
// All lookback traffic goes through L2 (__stcg/__ldcg) — no L1 in the protocol.
// ---------------------------------------------------------------------------
#define STAGE_BYTES 65536
#define OFF_AH 0
#define OFF_AL 16384
#define OFF_BH 32768
#define OFF_BL 49152
#define GEMM_SMEM (2 * STAGE_BYTES)
#define SROW 132   // floats per scan-buffer row (bank-shift 4/row)

__global__ void __launch_bounds__(256, 1)
gemm1_scan(const float* __restrict__ sp, const float* __restrict__ ap)
{
    extern __shared__ char smem[];
    const uint32_t sb = smem_u32(smem);
    const int tid = threadIdx.x, wid = tid >> 5, lane = tid & 31;

    __shared__ unsigned s_ticket;
    if (tid == 0) s_ticket = atomicAdd(&g_ticket, 1u);
    __syncthreads();
    const unsigned t = s_ticket;
    const int bn4 = t & 3;          // N tile 0..3
    const int bc = t >> 2;          // (b,c) chunk index 0..511 (c fast)
    const int c = bc & 63;
    const int bm = bc * 128;        // == b*8192 + c*128
    const int bn = bn4 * 128;

    // ---- stage loader ----
    auto load_stage = [&](int kb, int s) {
        uint32_t base = sb + s * STAGE_BYTES;
#pragma unroll
        for (int i = 0; i < 4; i++) {
            int chunk = tid + i * 256;
            int row = chunk >> 3, cc = chunk & 7;
            uint32_t so = swz((uint32_t)(row * 128 + cc * 16));
            size_t aoff = (size_t)(bm + row) * 512 + kb * 64 + cc * 8;
            size_t boff = (size_t)(bn + row) * 512 + kb * 64 + cc * 8;
            CP_ASYNC16(base + OFF_AH + so, g_xh + aoff);
            CP_ASYNC16(base + OFF_AL + so, g_xl + aoff);
            CP_ASYNC16(base + OFF_BH + so, g_W1h + boff);
            CP_ASYNC16(base + OFF_BL + so, g_W1l + boff);
        }
    };

    const int warp_m = (wid >> 2) * 64;
    const int warp_n = (wid & 3) * 32;
    const uint32_t aByte = (uint32_t)((warp_m + (lane & 15)) * 128 + (lane >> 4) * 16);
    const uint32_t bByte = (uint32_t)((warp_n + (lane & 7) + ((lane >> 4) << 3)) * 128
                                      + ((lane >> 3) & 1) * 16);

    float acc[4][4][4];
#pragma unroll
    for (int mf = 0; mf < 4; mf++)
#pragma unroll
        for (int nf = 0; nf < 4; nf++)
#pragma unroll
            for (int q = 0; q < 4; q++) acc[mf][nf][q] = 0.f;

    load_stage(0, 0); CP_COMMIT();
    load_stage(1, 1); CP_COMMIT();

    for (int kb = 0; kb < 8; kb++) {
        CP_WAIT1();
        __syncthreads();
        const uint32_t st = sb + (kb & 1) * STAGE_BYTES;
#pragma unroll
        for (int ks = 0; ks < 4; ks++) {
            const uint32_t ko = ks * 32;
            uint32_t a[4][4], b[2][4], bl[2][4];
#pragma unroll
            for (int mf = 0; mf < 4; mf++)
                LDSM4(a[mf], st + OFF_AH + swz(aByte + mf * 2048 + ko));
#pragma unroll
            for (int bi = 0; bi < 2; bi++)
                LDSM4(b[bi], st + OFF_BH + swz(bByte + bi * 2048 + ko));
#pragma unroll
            for (int mf = 0; mf < 4; mf++)
#pragma unroll
                for (int nf = 0; nf < 4; nf++)
                    mma16816(acc[mf][nf], a[mf], b[nf >> 1][(nf & 1) * 2], b[nf >> 1][(nf & 1) * 2 + 1]);
#pragma unroll
            for (int bi = 0; bi < 2; bi++)
                LDSM4(bl[bi], st + OFF_BL + swz(bByte + bi * 2048 + ko));
#pragma unroll
            for (int mf = 0; mf < 4; mf++)
#pragma unroll
                for (int nf = 0; nf < 4; nf++)
                    mma16816(acc[mf][nf], a[mf], bl[nf >> 1][(nf & 1) * 2], bl[nf >> 1][(nf & 1) * 2 + 1]);
#pragma unroll
            for (int mf = 0; mf < 4; mf++)
                LDSM4(a[mf], st + OFF_AL + swz(aByte + mf * 2048 + ko));
#pragma unroll
            for (int mf = 0; mf < 4; mf++)
#pragma unroll
                for (int nf = 0; nf < 4; nf++)
                    mma16816(acc[mf][nf], a[mf], b[nf >> 1][(nf & 1) * 2], b[nf >> 1][(nf & 1) * 2 + 1]);
        }
        __syncthreads();
        if (kb + 2 < 8) load_stage(kb + 2, kb & 1);
        CP_COMMIT();
    }

    // ---- stage Bu tile to smem (overlay stage buffers; all cp.async done) ----
    CP_WAIT0();
    __syncthreads();
    float* scanbuf = (float*)smem;
    const int r = lane >> 2, cq = (lane & 3) * 2;
#pragma unroll
    for (int mf = 0; mf < 4; mf++) {
#pragma unroll
        for (int nf = 0; nf < 4; nf++) {
            int row0 = warp_m + mf * 16 + r;
            int col = warp_n + nf * 8 + cq;
            *(float2*)(scanbuf + (size_t)row0 * SROW + col) =
                make_float2(acc[mf][nf][0], acc[mf][nf][1]);
            *(float2*)(scanbuf + (size_t)(row0 + 8) * SROW + col) =
                make_float2(acc[mf][nf][2], acc[mf][nf][3]);
        }
    }
    __syncthreads();

    // ---- scan phase: 64 workers (p-local = tid), warps 0-1 ----
    if (tid < 64) {
        const int pg = bn4 * 64 + tid;       // global p
        float s, s2, mB, mC, mD;
        get_params(sp, ap, pg, s, s2, mB, mC, mD);

        // Mp = M^128 by 7 squarings
        float m11 = 1.f, m12 = mB, m21 = mC, m22 = mD;
#pragma unroll
        for (int i = 0; i < LOG_LCH; i++) {
            float n11 = m11 * m11 + m12 * m21;
            float n12 = m12 * (m11 + m22);
            float n21 = m21 * (m11 + m22);
            float n22 = m12 * m21 + m22 * m22;
            m11 = n11; m12 = n12; m21 = n21; m22 = n22;
        }

        // local scan from zero -> chunk aggregate T
        float z1R = 0.f, z2R = 0.f, z1I = 0.f, z2I = 0.f;
#pragma unroll 4
        for (int j = 0; j < LCH; j++) {
            float2 v = *(const float2*)(scanbuf + (size_t)j * SROW + 2 * tid);
            float n1R = z1R + mB * z2R + s * v.x;
            z2R = mC * z1R + mD * z2R + s2 * v.x;
            z1R = n1R;
            float n1I = z1I + mB * z2I + s * v.y;
            z2I = mC * z1I + mD * z2I + s2 * v.y;
            z1I = n1I;
        }
        const float T1R = z1R, T2R = z2R, T1I = z1I, T2I = z2I;

        float4 S = make_float4(0.f, 0.f, 0.f, 0.f);
        if (c > 0) {
            // publish aggregate early (flag=1) — L2-coherent store
            __stcg(&g_agg[t * 64 + tid], make_float4(T1R, T2R, T1I, T2I));
            __threadfence();
            BAR64();
            if (tid == 0) atomicExch(&g_flag[t], 1);

            // lookback: S = T_{c-1} + Mp*T_{c-2} + ... (stop at inclusive)
            float w11 = 1.f, w12 = 0.f, w21 = 0.f, w22 = 1.f;
            int tj = (int)t - 4;
            while (true) {
                int f;
                do { f = *((volatile int*)(g_flag + tj)); } while (f == 0);
                __threadfence();
                if (f == 2) {
                    float4 v = __ldcg(&g_incl[tj * 64 + tid]);
                    S.x += w11 * v.x + w12 * v.y;  S.y += w21 * v.x + w22 * v.y;
                    S.z += w11 * v.z + w12 * v.w;  S.w += w21 * v.z + w22 * v.w;
                    break;
                } else {
                    float4 v = __ldcg(&g_agg[tj * 64 + tid]);
                    S.x += w11 * v.x + w12 * v.y;  S.y += w21 * v.x + w22 * v.y;
                    S.z += w11 * v.z + w12 * v.w;  S.w += w21 * v.z + w22 * v.w;
                    // Wpow *= Mp (powers of same matrix commute)
                    float n11 = w11 * m11 + w12 * m21, n12 = w11 * m12 + w12 * m22;
                    float n21 = w21 * m11 + w22 * m21, n22 = w21 * m12 + w22 * m22;
                    w11 = n11; w12 = n12; w21 = n21; w22 = n22;
                    tj -= 4;
                }
            }
        }
        // inclusive = T + Mp*S ; publish (flag=2)
        float4 inc;
        inc.x = T1R + m11 * S.x + m12 * S.y;
        inc.y = T2R + m21 * S.x + m22 * S.y;
        inc.z = T1I + m11 * S.z + m12 * S.w;
        inc.w = T2I + m21 * S.z + m22 * S.w;
        __stcg(&g_incl[t * 64 + tid], inc);
        __threadfence();
        BAR64();
        if (tid == 0) atomicExch(&g_flag[t], 2);

        // re-scan from prefix S, write ys = z2 as bf16 hi/lo
        z1R = S.x; z2R = S.y; z1I = S.z; z2I = S.w;
        uint32_t* Yh = (uint32_t*)(g_yh + (size_t)bm * 512 + bn) + tid;
        uint32_t* Yl = (uint32_t*)(g_yl + (size_t)bm * 512 + bn) + tid;
#pragma unroll 4
        for (int j = 0; j < LCH; j++) {
            float2 v = *(const float2*)(scanbuf + (size_t)j * SROW + 2 * tid);
            float n1R = z1R + mB * z2R + s * v.x;
            z2R = mC * z1R + mD * z2R + s2 * v.x;
            z1R = n1R;
            float n1I = z1I + mB * z2I + s * v.y;
            z2I = mC * z1I + mD * z2I + s2 * v.y;
            z1I = n1I;
            uint32_t lo;
            uint32_t hi = pack_hi_lo(z2R, z2I, lo);
            Yh[(size_t)j * 256] = hi;
            Yl[(size_t)j * 256] = lo;
        }
    }
}

// ---------------------------------------------------------------------------
// GEMM2: y[m][h] = sum_k ys[m][k]*W2[h][k] + D[h]*x[m][h]   (bf16x3 split)
// ---------------------------------------------------------------------------
__global__ void __launch_bounds__(256, 1)
gemm2(const float* __restrict__ Xin, float* __restrict__ Yout,
      const float* __restrict__ Dvec)
{
    extern __shared__ char smem[];
    const uint32_t sb = smem_u32(smem);
    const int tid = threadIdx.x, wid = tid >> 5, lane = tid & 31;
    const int bm = blockIdx.y * 128, bn = blockIdx.x * 128;

    auto load_stage = [&](int kb, int s) {
        uint32_t base = sb + s * STAGE_BYTES;
#pragma unroll
        for (int i = 0; i < 4; i++) {
            int chunk = tid + i * 256;
            int row = chunk >> 3, cc = chunk & 7;
            uint32_t so = swz((uint32_t)(row * 128 + cc * 16));
            size_t aoff = (size_t)(bm + row) * 512 + kb * 64 + cc * 8;
            size_t boff = (size_t)(bn + row) * 512 + kb * 64 + cc * 8;
            CP_ASYNC16(base + OFF_AH + so, g_yh + aoff);
            CP_ASYNC16(base + OFF_AL + so, g_yl + aoff);
            CP_ASYNC16(base + OFF_BH + so, g_W2h + boff);
            CP_ASYNC16(base + OFF_BL + so, g_W2l + boff);
        }
    };

    const int warp_m = (wid >> 2) * 64;
    const int warp_n = (wid & 3) * 32;
    const uint32_t aByte = (uint32_t)((warp_m + (lane & 15)) * 128 + (lane >> 4) * 16);
    const uint32_t bByte = (uint32_t)((warp_n + (lane & 7) + ((lane >> 4) << 3)) * 128
                                      + ((lane >> 3) & 1) * 16);

    float acc[4][4][4];
#pragma unroll
    for (int mf = 0; mf < 4; mf++)
#pragma unroll
        for (int nf = 0; nf < 4; nf++)
#pragma unroll
            for (int q = 0; q < 4; q++) acc[mf][nf][q] = 0.f;

    load_stage(0, 0); CP_COMMIT();
    load_stage(1, 1); CP_COMMIT();

    for (int kb = 0; kb < 8; kb++) {
        CP_WAIT1();
        __syncthreads();
        const uint32_t st = sb + (kb & 1) * STAGE_BYTES;
#pragma unroll
        for (int ks = 0; ks < 4; ks++) {
            const uint32_t ko = ks * 32;
            uint32_t a[4][4], b[2][4], bl[2][4];
#pragma unroll
            for (int mf = 0; mf < 4; mf++)
                LDSM4(a[mf], st + OFF_AH + swz(aByte + mf * 2048 + ko));
#pragma unroll
            for (int bi = 0; bi < 2; bi++)
                LDSM4(b[bi], st + OFF_BH + swz(bByte + bi * 2048 + ko));
#pragma unroll
            for (int mf = 0; mf < 4; mf++)
#pragma unroll
                for (int nf = 0; nf < 4; nf++)
                    mma16816(acc[mf][nf], a[mf], b[nf >> 1][(nf & 1) * 2], b[nf >> 1][(nf & 1) * 2 + 1]);
#pragma unroll
            for (int bi = 0; bi < 2; bi++)
                LDSM4(bl[bi], st + OFF_BL + swz(bByte + bi * 2048 + ko));
#pragma unroll
            for (int mf = 0; mf < 4; mf++)
#pragma unroll
                for (int nf = 0; nf < 4; nf++)
                    mma16816(acc[mf][nf], a[mf], bl[nf >> 1][(nf & 1) * 2], bl[nf >> 1][(nf & 1) * 2 + 1]);
#pragma unroll
            for (int mf = 0; mf < 4; mf++)
                LDSM4(a[mf], st + OFF_AL + swz(aByte + mf * 2048 + ko));
#pragma unroll
            for (int mf = 0; mf < 4; mf++)
#pragma unroll
                for (int nf = 0; nf < 4; nf++)
                    mma16816(acc[mf][nf], a[mf], b[nf >> 1][(nf & 1) * 2], b[nf >> 1][(nf & 1) * 2 + 1]);
        }
        __syncthreads();
        if (kb + 2 < 8) load_stage(kb + 2, kb & 1);
        CP_COMMIT();
    }

    const int r = lane >> 2, cq = (lane & 3) * 2;
#pragma unroll
    for (int mf = 0; mf < 4; mf++) {
#pragma unroll
        for (int nf = 0; nf < 4; nf++) {
            int row0 = bm + warp_m + mf * 16 + r;
            int col = bn + warp_n + nf * 8 + cq;
            float2 v0 = make_float2(acc[mf][nf][0], acc[mf][nf][1]);
            float2 v1 = make_float2(acc[mf][nf][2], acc[mf][nf][3]);
            float2 dv = *(const float2*)(Dvec + col);
            float2 x0 = *(const float2*)(Xin + (size_t)row0 * 512 + col);
            float2 x1 = *(const float2*)(Xin + (size_t)(row0 + 8) * 512 + col);
            v0.x += dv.x * x0.x; v0.y += dv.y * x0.y;
            v1.x += dv.x * x1.x; v1.y += dv.y * x1.y;
            *(float2*)(Yout + (size_t)row0 * 512 + col) = v0;
            *(float2*)(Yout + (size_t)(row0 + 8) * 512 + col) = v1;
        }
    }
}

// ---------------------------------------------------------------------------
// Launch: prep -> fused GEMM1+scan -> GEMM2(+D*x)
// ---------------------------------------------------------------------------
extern "C" void kernel_launch(void* const* d_in, const int* in_sizes, int n_in,
                              void* d_out, int out_size)
{
    const float* x  = (const float*)d_in[0];
    const float* sp = (const float*)d_in[1];
    const float* ap = (const float*)d_in[2];
    const float* B  = (const float*)d_in[3];
    const float* C  = (const float*)d_in[4];
    const float* D  = (const float*)d_in[5];
    float* y = (float*)d_out;

    cudaFuncSetAttribute(gemm1_scan, cudaFuncAttributeMaxDynamicSharedMemorySize, GEMM_SMEM);
    cudaFuncSetAttribute(gemm2, cudaFuncAttributeMaxDynamicSharedMemorySize, GEMM_SMEM);

    prep_weights<<<512, 256>>>(B, C);
    prep_x<<<32768, 256>>>(x);

    gemm1_scan<<<NCHAIN, 256, GEMM_SMEM>>>(sp, ap);

    dim3 g2(4, 512);
    gemm2<<<g2, 256, GEMM_SMEM>>>(x, y, D);
}